// round 3
// baseline (speedup 1.0000x reference)
#include <cuda_runtime.h>
#include <cuda_bf16.h>

#define DMODEL 512
#define NHEAD 8
#define HDIM 64
#define MAX_T 4096

typedef unsigned long long u64;

// Packed fp32x2 helpers (sm_103a FFMA2 — 2 fp32 FMA per issue)
__device__ __forceinline__ u64 pack2(float v) {
    u64 r; asm("mov.b64 %0, {%1, %1};" : "=l"(r) : "f"(v)); return r;
}
__device__ __forceinline__ void fma2(u64& d, u64 a, u64 b) {
    asm("fma.rn.f32x2 %0, %1, %2, %3;" : "=l"(d) : "l"(a), "l"(b), "l"(d));
}
__device__ __forceinline__ u64 mul2(u64 a, u64 b) {
    u64 r; asm("mul.rn.f32x2 %0, %1, %2;" : "=l"(r) : "l"(a), "l"(b)); return r;
}
__device__ __forceinline__ float2 unpk(u64 v) {
    float2 r; asm("mov.b64 {%0, %1}, %2;" : "=f"(r.x), "=f"(r.y) : "l"(v)); return r;
}

// Scratch (no allocation allowed)
__device__ float g_Q[MAX_T * DMODEL];
__device__ float g_K[MAX_T * DMODEL];
__device__ float g_V[MAX_T * DMODEL];
__device__ float g_O[MAX_T * DMODEL];

// ---------------------------------------------------------------------------
// Projection GEMM: C[T,512] = (A (+ P)) @ W + bias
// BM=64, BN=128, BK=16, 256 threads, 4x8 per thread, FFMA2 inner loop.
// ---------------------------------------------------------------------------
__global__ void __launch_bounds__(256) gemm_proj(
    const float* __restrict__ A, const float* __restrict__ P,
    const float* __restrict__ W, const float* __restrict__ bias,
    float* __restrict__ C, int T)
{
    __shared__ float As[16][64];    // As[k][m] (transposed)
    __shared__ float Bs[16][128];   // Bs[k][n]

    const int tid = threadIdx.x;
    const int tx = tid & 15;          // n: 8 cols each
    const int ty = tid >> 4;          // m: 4 rows each
    const int row0 = blockIdx.x * 64;
    const int col0 = blockIdx.y * 128;

    u64 acc[4][4];                    // [row i][col-pair j2] -> 4x8 floats
#pragma unroll
    for (int i = 0; i < 4; i++)
#pragma unroll
        for (int j = 0; j < 4; j++) acc[i][j] = 0ull;

    for (int k0 = 0; k0 < DMODEL; k0 += 16) {
        // A tile: 64 rows x 16 k, transposed
        {
            const int r = tid >> 2;
            const int c = (tid & 3) * 4;
            float4 av = *(const float4*)&A[(size_t)(row0 + r) * DMODEL + k0 + c];
            if (P) {
                float4 pv = *(const float4*)&P[(size_t)(row0 + r) * DMODEL + k0 + c];
                av.x += pv.x; av.y += pv.y; av.z += pv.z; av.w += pv.w;
            }
            As[c + 0][r] = av.x;
            As[c + 1][r] = av.y;
            As[c + 2][r] = av.z;
            As[c + 3][r] = av.w;
        }
        // B tile: 16 k x 128 n
        {
            const int r = tid >> 4;          // 0..15
            const int cb = (tid & 15) * 8;   // 0..120
            *(float4*)&Bs[r][cb]     = *(const float4*)&W[(size_t)(k0 + r) * DMODEL + col0 + cb];
            *(float4*)&Bs[r][cb + 4] = *(const float4*)&W[(size_t)(k0 + r) * DMODEL + col0 + cb + 4];
        }
        __syncthreads();

#pragma unroll
        for (int kk = 0; kk < 16; kk++) {
            float4 a4 = *(const float4*)&As[kk][ty * 4];
            u64 ad0 = pack2(a4.x), ad1 = pack2(a4.y), ad2 = pack2(a4.z), ad3 = pack2(a4.w);
            ulonglong2 b0 = *(const ulonglong2*)&Bs[kk][tx * 8];
            ulonglong2 b1 = *(const ulonglong2*)&Bs[kk][tx * 8 + 4];
            fma2(acc[0][0], ad0, b0.x); fma2(acc[0][1], ad0, b0.y);
            fma2(acc[0][2], ad0, b1.x); fma2(acc[0][3], ad0, b1.y);
            fma2(acc[1][0], ad1, b0.x); fma2(acc[1][1], ad1, b0.y);
            fma2(acc[1][2], ad1, b1.x); fma2(acc[1][3], ad1, b1.y);
            fma2(acc[2][0], ad2, b0.x); fma2(acc[2][1], ad2, b0.y);
            fma2(acc[2][2], ad2, b1.x); fma2(acc[2][3], ad2, b1.y);
            fma2(acc[3][0], ad3, b0.x); fma2(acc[3][1], ad3, b0.y);
            fma2(acc[3][2], ad3, b1.x); fma2(acc[3][3], ad3, b1.y);
        }
        __syncthreads();
    }

    // Epilogue: bias + store
    const int cbase = col0 + tx * 8;
    float4 bv0 = *(const float4*)&bias[cbase];
    float4 bv1 = *(const float4*)&bias[cbase + 4];
#pragma unroll
    for (int i = 0; i < 4; i++) {
        const int r = row0 + ty * 4 + i;
        float2 p0 = unpk(acc[i][0]), p1 = unpk(acc[i][1]);
        float2 p2 = unpk(acc[i][2]), p3 = unpk(acc[i][3]);
        float4 o0 = make_float4(p0.x + bv0.x, p0.y + bv0.y, p1.x + bv0.z, p1.y + bv0.w);
        float4 o1 = make_float4(p2.x + bv1.x, p2.y + bv1.y, p3.x + bv1.z, p3.y + bv1.w);
        *(float4*)&C[(size_t)r * DMODEL + cbase]     = o0;
        *(float4*)&C[(size_t)r * DMODEL + cbase + 4] = o1;
    }
}

// ---------------------------------------------------------------------------
// Block-diagonal flash attention with FFMA2 inner loops.
// grid: (q-tiles upper bound, NHEAD); 256 threads (16x16); 64KB smem.
// ---------------------------------------------------------------------------
#define ATTN_SMEM (4 * 64 * 64 * sizeof(float))

__global__ void __launch_bounds__(256) attn_kernel(
    const float* __restrict__ Q, const float* __restrict__ K,
    const float* __restrict__ V, float* __restrict__ O,
    const int* __restrict__ channels, int nseg, int T)
{
    int csum = 0;
    for (int i = 0; i < nseg; i++) csum += channels[i];
    const int Stok = T / csum;

    const int tile = blockIdx.x;
    const int h = blockIdx.y;

    int seg_start = 0, seg_len = 0, t_in_seg = -1;
    {
        int toff = 0, soff = 0;
        for (int i = 0; i < nseg; i++) {
            int L = channels[i] * Stok;
            int nt = (L + 63) >> 6;
            if (tile < toff + nt) { t_in_seg = tile - toff; seg_start = soff; seg_len = L; break; }
            toff += nt; soff += L;
        }
    }
    if (t_in_seg < 0) return;

    const int q0 = seg_start + t_in_seg * 64;
    const int qlen = min(64, seg_len - t_in_seg * 64);

    extern __shared__ float sm[];
    float* Qs = sm;                 // [d][q] 64x64
    float* Ks = sm + 64 * 64;       // [d][k] 64x64
    float* Vs = sm + 2 * 64 * 64;   // [k][hd] 64x64
    float* Ps = sm + 3 * 64 * 64;   // [q][k] 64x64

    const int tid = threadIdx.x;
    const int tx = tid & 15;
    const int ty = tid >> 4;

    // Load Q transposed: Qs[d][q]
    {
        const int r = tid >> 2;
        const int dbase = (tid & 3) * 16;
        const float* Qg = Q + (size_t)(q0 + r) * DMODEL + h * HDIM;
#pragma unroll
        for (int v = 0; v < 4; v++) {
            int d = dbase + v * 4;
            float4 qv = make_float4(0.f, 0.f, 0.f, 0.f);
            if (r < qlen) qv = *(const float4*)&Qg[d];
            Qs[(d + 0) * 64 + r] = qv.x;
            Qs[(d + 1) * 64 + r] = qv.y;
            Qs[(d + 2) * 64 + r] = qv.z;
            Qs[(d + 3) * 64 + r] = qv.w;
        }
    }

    float m_i[4], l_i[4];
    u64 o2[4][2];
#pragma unroll
    for (int i = 0; i < 4; i++) {
        m_i[i] = -1e30f; l_i[i] = 0.f;
        o2[i][0] = 0ull; o2[i][1] = 0ull;
    }

    const int nkt = (seg_len + 63) >> 6;
    const float scale = 0.125f;

    for (int kt = 0; kt < nkt; kt++) {
        const int k0 = seg_start + kt * 64;
        const int klen = min(64, seg_len - kt * 64);

        __syncthreads();

        // Load K transposed (Ks[d][k]) and V natural (Vs[k][hd])
        {
            const int r = tid >> 2;
            const int dbase = (tid & 3) * 16;
            const float* Kg = K + (size_t)(k0 + r) * DMODEL + h * HDIM;
            const float* Vg = V + (size_t)(k0 + r) * DMODEL + h * HDIM;
#pragma unroll
            for (int v = 0; v < 4; v++) {
                int d = dbase + v * 4;
                float4 kv = make_float4(0.f, 0.f, 0.f, 0.f);
                float4 vv = make_float4(0.f, 0.f, 0.f, 0.f);
                if (r < klen) { kv = *(const float4*)&Kg[d]; vv = *(const float4*)&Vg[d]; }
                Ks[(d + 0) * 64 + r] = kv.x;
                Ks[(d + 1) * 64 + r] = kv.y;
                Ks[(d + 2) * 64 + r] = kv.z;
                *(float4*)&Vs[r * 64 + d] = vv;
                Ks[(d + 3) * 64 + r] = kv.w;
            }
        }
        __syncthreads();

        // Scores via FFMA2: s2[i][j2] over pairs of key cols
        u64 s2[4][2];
#pragma unroll
        for (int i = 0; i < 4; i++) { s2[i][0] = 0ull; s2[i][1] = 0ull; }

#pragma unroll 8
        for (int d = 0; d < 64; d++) {
            float4 q4 = *(const float4*)&Qs[d * 64 + ty * 4];
            ulonglong2 k2 = *(const ulonglong2*)&Ks[d * 64 + tx * 4];
            u64 qd0 = pack2(q4.x), qd1 = pack2(q4.y), qd2 = pack2(q4.z), qd3 = pack2(q4.w);
            fma2(s2[0][0], qd0, k2.x); fma2(s2[0][1], qd0, k2.y);
            fma2(s2[1][0], qd1, k2.x); fma2(s2[1][1], qd1, k2.y);
            fma2(s2[2][0], qd2, k2.x); fma2(s2[2][1], qd2, k2.y);
            fma2(s2[3][0], qd3, k2.x); fma2(s2[3][1], qd3, k2.y);
        }

        // Online softmax (scalar, per row)
#pragma unroll
        for (int i = 0; i < 4; i++) {
            float2 sa = unpk(s2[i][0]), sb = unpk(s2[i][1]);
            float sv0 = sa.x * scale, sv1 = sa.y * scale;
            float sv2 = sb.x * scale, sv3 = sb.y * scale;
            if (tx * 4 + 0 >= klen) sv0 = -1e30f;
            if (tx * 4 + 1 >= klen) sv1 = -1e30f;
            if (tx * 4 + 2 >= klen) sv2 = -1e30f;
            if (tx * 4 + 3 >= klen) sv3 = -1e30f;

            float mx = fmaxf(fmaxf(sv0, sv1), fmaxf(sv2, sv3));
#pragma unroll
            for (int off = 8; off >= 1; off >>= 1)
                mx = fmaxf(mx, __shfl_xor_sync(0xffffffffu, mx, off));
            float mnew = fmaxf(m_i[i], mx);
            float alpha = __expf(m_i[i] - mnew);
            m_i[i] = mnew;

            float4 p4;
            p4.x = __expf(sv0 - mnew);
            p4.y = __expf(sv1 - mnew);
            p4.z = __expf(sv2 - mnew);
            p4.w = __expf(sv3 - mnew);

            float rs = p4.x + p4.y + p4.z + p4.w;
#pragma unroll
            for (int off = 8; off >= 1; off >>= 1)
                rs += __shfl_xor_sync(0xffffffffu, rs, off);
            l_i[i] = l_i[i] * alpha + rs;

            u64 al = pack2(alpha);
            o2[i][0] = mul2(o2[i][0], al);
            o2[i][1] = mul2(o2[i][1], al);

            *(float4*)&Ps[(ty * 4 + i) * 64 + tx * 4] = p4;
        }
        __syncthreads();

        // o += P @ V, kk stepped by 4; Ps read as broadcast float4 per row
#pragma unroll 4
        for (int kk0 = 0; kk0 < 64; kk0 += 4) {
            float4 pr0 = *(const float4*)&Ps[(ty * 4 + 0) * 64 + kk0];
            float4 pr1 = *(const float4*)&Ps[(ty * 4 + 1) * 64 + kk0];
            float4 pr2 = *(const float4*)&Ps[(ty * 4 + 2) * 64 + kk0];
            float4 pr3 = *(const float4*)&Ps[(ty * 4 + 3) * 64 + kk0];
            const float p0[4] = {pr0.x, pr0.y, pr0.z, pr0.w};
            const float p1[4] = {pr1.x, pr1.y, pr1.z, pr1.w};
            const float p2[4] = {pr2.x, pr2.y, pr2.z, pr2.w};
            const float p3[4] = {pr3.x, pr3.y, pr3.z, pr3.w};
#pragma unroll
            for (int t = 0; t < 4; t++) {
                ulonglong2 v2 = *(const ulonglong2*)&Vs[(kk0 + t) * 64 + tx * 4];
                u64 pd0 = pack2(p0[t]), pd1 = pack2(p1[t]);
                u64 pd2 = pack2(p2[t]), pd3 = pack2(p3[t]);
                fma2(o2[0][0], pd0, v2.x); fma2(o2[0][1], pd0, v2.y);
                fma2(o2[1][0], pd1, v2.x); fma2(o2[1][1], pd1, v2.y);
                fma2(o2[2][0], pd2, v2.x); fma2(o2[2][1], pd2, v2.y);
                fma2(o2[3][0], pd3, v2.x); fma2(o2[3][1], pd3, v2.y);
            }
        }
    }

    // Normalize and store
#pragma unroll
    for (int i = 0; i < 4; i++) {
        const int qr = ty * 4 + i;
        if (qr < qlen) {
            float inv = 1.0f / l_i[i];
            float2 oa = unpk(o2[i][0]), ob = unpk(o2[i][1]);
            float4 out = make_float4(oa.x * inv, oa.y * inv, ob.x * inv, ob.y * inv);
            *(float4*)&O[(size_t)(q0 + qr) * DMODEL + h * HDIM + tx * 4] = out;
        }
    }
}

// ---------------------------------------------------------------------------
extern "C" void kernel_launch(void* const* d_in, const int* in_sizes, int n_in,
                              void* d_out, int out_size)
{
    const float* xq  = (const float*)d_in[0];
    const float* xk  = (const float*)d_in[1];
    const float* pos = (const float*)d_in[2];
    const int* channels = (const int*)d_in[3];
    const float* Wq = (const float*)d_in[4];  const float* bq = (const float*)d_in[5];
    const float* Wk = (const float*)d_in[6];  const float* bk = (const float*)d_in[7];
    const float* Wv = (const float*)d_in[8];  const float* bv = (const float*)d_in[9];
    const float* Wo = (const float*)d_in[10]; const float* bo = (const float*)d_in[11];

    const int T = in_sizes[0] / DMODEL;     // 3136
    const int nseg = in_sizes[3];           // 4

    float *pQ, *pK, *pV, *pO;
    cudaGetSymbolAddress((void**)&pQ, g_Q);
    cudaGetSymbolAddress((void**)&pK, g_K);
    cudaGetSymbolAddress((void**)&pV, g_V);
    cudaGetSymbolAddress((void**)&pO, g_O);

    dim3 blk(256);
    dim3 grd(T / 64, DMODEL / 128);

    gemm_proj<<<grd, blk>>>(xq, pos, Wq, bq, pQ, T);
    gemm_proj<<<grd, blk>>>(xk, pos, Wk, bk, pK, T);
    gemm_proj<<<grd, blk>>>(xk, nullptr, Wv, bv, pV, T);

    cudaFuncSetAttribute(attn_kernel, cudaFuncAttributeMaxDynamicSharedMemorySize,
                         (int)ATTN_SMEM);
    dim3 agrd(T / 64 + nseg, NHEAD);
    attn_kernel<<<agrd, blk, ATTN_SMEM>>>(pQ, pK, pV, pO, channels, nseg, T);

    gemm_proj<<<grd, blk>>>(pO, nullptr, Wo, bo, (float*)d_out, T);
}

// round 6
// speedup vs baseline: 1.2755x; 1.2755x over previous
#include <cuda_runtime.h>
#include <cuda_bf16.h>

#define DMODEL 512
#define NHEAD 8
#define HDIM 64
#define MAX_T 4096
#define CHUNK_THRESH 10   // segments with nkt > this split into 2 K-chunks

// Scratch (no allocation allowed; __device__ globals)
__device__ float g_Q[MAX_T * DMODEL];
__device__ float g_K[MAX_T * DMODEL];
__device__ float g_V[MAX_T * DMODEL];
__device__ float g_O[MAX_T * DMODEL];
__device__ float g_Op0[MAX_T * DMODEL];    // partial unnormalized O, chunk 0
__device__ float g_Op1[MAX_T * DMODEL];    // partial unnormalized O, chunk 1
__device__ float2 g_ml0[MAX_T * NHEAD];    // (m, l) chunk 0
__device__ float2 g_ml1[MAX_T * NHEAD];    // (m, l) chunk 1

// ---------------------------------------------------------------------------
// Projection GEMM (R1 version — measured-good): C = (A (+P)) @ W + bias
// BM=64, BN=64, BK=16, 256 threads, 4x4 microtile.
// ---------------------------------------------------------------------------
__global__ void __launch_bounds__(256) gemm_proj(
    const float* __restrict__ A, const float* __restrict__ P,
    const float* __restrict__ W, const float* __restrict__ bias,
    float* __restrict__ C, int T)
{
    __shared__ float As[16][64];   // As[k][m]
    __shared__ float Bs[16][64];   // Bs[k][n]

    const int tid = threadIdx.x;
    const int tx = tid & 15;
    const int ty = tid >> 4;
    const int row0 = blockIdx.x * 64;
    const int col0 = blockIdx.y * 64;

    float acc[4][4] = {};

    for (int k0 = 0; k0 < DMODEL; k0 += 16) {
        {
            const int r = tid >> 2;
            const int c = (tid & 3) * 4;
            float4 av = *(const float4*)&A[(size_t)(row0 + r) * DMODEL + k0 + c];
            if (P) {
                float4 pv = *(const float4*)&P[(size_t)(row0 + r) * DMODEL + k0 + c];
                av.x += pv.x; av.y += pv.y; av.z += pv.z; av.w += pv.w;
            }
            As[c + 0][r] = av.x;
            As[c + 1][r] = av.y;
            As[c + 2][r] = av.z;
            As[c + 3][r] = av.w;
        }
        {
            const int r = tid >> 4;
            const int c = (tid & 15) * 4;
            *(float4*)&Bs[r][c] = *(const float4*)&W[(size_t)(k0 + r) * DMODEL + col0 + c];
        }
        __syncthreads();

#pragma unroll
        for (int kk = 0; kk < 16; kk++) {
            float4 a4 = *(const float4*)&As[kk][ty * 4];
            float4 b4 = *(const float4*)&Bs[kk][tx * 4];
            float af[4] = {a4.x, a4.y, a4.z, a4.w};
            float bf[4] = {b4.x, b4.y, b4.z, b4.w};
#pragma unroll
            for (int i = 0; i < 4; i++)
#pragma unroll
                for (int j = 0; j < 4; j++)
                    acc[i][j] += af[i] * bf[j];
        }
        __syncthreads();
    }

#pragma unroll
    for (int i = 0; i < 4; i++) {
        const int r = row0 + ty * 4 + i;
        const int c = col0 + tx * 4;
        float4 out;
        out.x = acc[i][0] + bias[c + 0];
        out.y = acc[i][1] + bias[c + 1];
        out.z = acc[i][2] + bias[c + 2];
        out.w = acc[i][3] + bias[c + 3];
        *(float4*)&C[(size_t)r * DMODEL + c] = out;
    }
}

// ---------------------------------------------------------------------------
// Block-diagonal flash attention, K-split into chunks for load balance.
// Writes UNNORMALIZED partial O plus (m, l) per (token, head) per chunk.
// Smem 48KB: Qs[d][q] | Ks[d][k] (aliased by Ps[q][k]) | Vs[k][hd].
// ---------------------------------------------------------------------------
#define ATTN_SMEM (3 * 64 * 64 * sizeof(float))

__global__ void __launch_bounds__(256, 4) attn_kernel(
    const float* __restrict__ Q, const float* __restrict__ K,
    const float* __restrict__ V,
    float* __restrict__ Op0, float* __restrict__ Op1,
    float2* __restrict__ ml0, float2* __restrict__ ml1,
    const int* __restrict__ channels, int nseg, int T)
{
    int csum = 0;
    for (int i = 0; i < nseg; i++) csum += channels[i];
    const int Stok = T / csum;

    const int bx = blockIdx.x;
    const int h = blockIdx.y;

    // Map block -> (segment, q-tile, k-chunk)
    int tile = -1, chunk = 0, seg_start = 0, seg_len = 0;
    {
        int toff = 0, soff = 0;
        for (int i = 0; i < nseg; i++) {
            int L = channels[i] * Stok;
            int nkt = (L + 63) >> 6;
            int nc = (nkt > CHUNK_THRESH) ? 2 : 1;
            int span = nkt * nc;               // nt == nkt (square block)
            if (bx < toff + span) {
                int local = bx - toff;
                tile = local / nc;
                chunk = local % nc;
                seg_start = soff;
                seg_len = L;
                break;
            }
            toff += span; soff += L;
        }
    }
    if (tile < 0) return;

    const int nkt = (seg_len + 63) >> 6;
    const int nc = (nkt > CHUNK_THRESH) ? 2 : 1;
    const int clen = (nkt + nc - 1) / nc;
    const int kt0 = chunk * clen;
    const int kt1 = min(nkt, kt0 + clen);

    const int q0 = seg_start + tile * 64;
    const int qlen = min(64, seg_len - tile * 64);

    extern __shared__ float sm[];
    float* Qs = sm;                 // [d][q] 64x64
    float* Ks = sm + 64 * 64;       // [d][k] 64x64  (reused as Ps[q][k])
    float* Ps = Ks;
    float* Vs = sm + 2 * 64 * 64;   // [k][hd] 64x64

    const int tid = threadIdx.x;
    const int tx = tid & 15;
    const int ty = tid >> 4;

    // Load Q transposed: Qs[d][q]
    {
        const int r = tid >> 2;
        const int dbase = (tid & 3) * 16;
        const float* Qg = Q + (size_t)(q0 + r) * DMODEL + h * HDIM;
#pragma unroll
        for (int v = 0; v < 4; v++) {
            int d = dbase + v * 4;
            float4 qv = make_float4(0.f, 0.f, 0.f, 0.f);
            if (r < qlen) qv = *(const float4*)&Qg[d];
            Qs[(d + 0) * 64 + r] = qv.x;
            Qs[(d + 1) * 64 + r] = qv.y;
            Qs[(d + 2) * 64 + r] = qv.z;
            Qs[(d + 3) * 64 + r] = qv.w;
        }
    }

    float m_i[4], l_i[4], o[4][4];
#pragma unroll
    for (int i = 0; i < 4; i++) {
        m_i[i] = -1e30f; l_i[i] = 0.f;
#pragma unroll
        for (int j = 0; j < 4; j++) o[i][j] = 0.f;
    }

    const float scale = 0.125f;   // 1/sqrt(64)

    for (int kt = kt0; kt < kt1; kt++) {
        const int k0 = seg_start + kt * 64;
        const int klen = min(64, seg_len - kt * 64);

        __syncthreads();   // prior iter done reading Ps/Vs before overwrite

        // Load K transposed (Ks[d][k]) and V natural (Vs[k][hd])
        {
            const int r = tid >> 2;
            const int dbase = (tid & 3) * 16;
            const float* Kg = K + (size_t)(k0 + r) * DMODEL + h * HDIM;
            const float* Vg = V + (size_t)(k0 + r) * DMODEL + h * HDIM;
#pragma unroll
            for (int v = 0; v < 4; v++) {
                int d = dbase + v * 4;
                float4 kv = make_float4(0.f, 0.f, 0.f, 0.f);
                float4 vv = make_float4(0.f, 0.f, 0.f, 0.f);
                if (r < klen) { kv = *(const float4*)&Kg[d]; vv = *(const float4*)&Vg[d]; }
                Ks[(d + 0) * 64 + r] = kv.x;
                Ks[(d + 1) * 64 + r] = kv.y;
                Ks[(d + 2) * 64 + r] = kv.z;
                *(float4*)&Vs[r * 64 + d] = vv;
                Ks[(d + 3) * 64 + r] = kv.w;
            }
        }
        __syncthreads();

        // Scores s[i][j] = sum_d Qs[d][ty*4+i] * Ks[d][tx*4+j]
        float s[4][4] = {};
#pragma unroll 8
        for (int d = 0; d < 64; d++) {
            float4 q4 = *(const float4*)&Qs[d * 64 + ty * 4];
            float4 k4 = *(const float4*)&Ks[d * 64 + tx * 4];
            float qf[4] = {q4.x, q4.y, q4.z, q4.w};
            float kf[4] = {k4.x, k4.y, k4.z, k4.w};
#pragma unroll
            for (int i = 0; i < 4; i++)
#pragma unroll
                for (int j = 0; j < 4; j++)
                    s[i][j] += qf[i] * kf[j];
        }

        __syncthreads();   // all warps done reading Ks before Ps overwrite

        // Online softmax per row; write P into (aliased) Ps
#pragma unroll
        for (int i = 0; i < 4; i++) {
            float sv[4];
#pragma unroll
            for (int j = 0; j < 4; j++) {
                sv[j] = s[i][j] * scale;
                if (tx * 4 + j >= klen) sv[j] = -1e30f;
            }
            float mx = fmaxf(fmaxf(sv[0], sv[1]), fmaxf(sv[2], sv[3]));
#pragma unroll
            for (int off = 8; off >= 1; off >>= 1)
                mx = fmaxf(mx, __shfl_xor_sync(0xffffffffu, mx, off));
            float mnew = fmaxf(m_i[i], mx);
            float alpha = __expf(m_i[i] - mnew);
            m_i[i] = mnew;

            float4 p4;
            p4.x = __expf(sv[0] - mnew);
            p4.y = __expf(sv[1] - mnew);
            p4.z = __expf(sv[2] - mnew);
            p4.w = __expf(sv[3] - mnew);

            float rs = p4.x + p4.y + p4.z + p4.w;
#pragma unroll
            for (int off = 8; off >= 1; off >>= 1)
                rs += __shfl_xor_sync(0xffffffffu, rs, off);
            l_i[i] = l_i[i] * alpha + rs;

#pragma unroll
            for (int j = 0; j < 4; j++) o[i][j] *= alpha;

            *(float4*)&Ps[(ty * 4 + i) * 64 + tx * 4] = p4;
        }
        __syncthreads();

        // o += P @ V (Ps read as float4 per row, V as float4)
#pragma unroll 4
        for (int kk0 = 0; kk0 < 64; kk0 += 4) {
            float4 pr0 = *(const float4*)&Ps[(ty * 4 + 0) * 64 + kk0];
            float4 pr1 = *(const float4*)&Ps[(ty * 4 + 1) * 64 + kk0];
            float4 pr2 = *(const float4*)&Ps[(ty * 4 + 2) * 64 + kk0];
            float4 pr3 = *(const float4*)&Ps[(ty * 4 + 3) * 64 + kk0];
            const float p0[4] = {pr0.x, pr0.y, pr0.z, pr0.w};
            const float p1[4] = {pr1.x, pr1.y, pr1.z, pr1.w};
            const float p2[4] = {pr2.x, pr2.y, pr2.z, pr2.w};
            const float p3[4] = {pr3.x, pr3.y, pr3.z, pr3.w};
#pragma unroll
            for (int t = 0; t < 4; t++) {
                float4 v4 = *(const float4*)&Vs[(kk0 + t) * 64 + tx * 4];
                float vf[4] = {v4.x, v4.y, v4.z, v4.w};
#pragma unroll
                for (int j = 0; j < 4; j++) {
                    o[0][j] += p0[t] * vf[j];
                    o[1][j] += p1[t] * vf[j];
                    o[2][j] += p2[t] * vf[j];
                    o[3][j] += p3[t] * vf[j];
                }
            }
        }
    }

    // Store unnormalized partials + (m, l)
    float* Op = (chunk == 0) ? Op0 : Op1;
    float2* ml = (chunk == 0) ? ml0 : ml1;
#pragma unroll
    for (int i = 0; i < 4; i++) {
        const int qr = ty * 4 + i;
        if (qr < qlen) {
            float4 out = make_float4(o[i][0], o[i][1], o[i][2], o[i][3]);
            *(float4*)&Op[(size_t)(q0 + qr) * DMODEL + h * HDIM + tx * 4] = out;
            if (tx == 0)
                ml[(q0 + qr) * NHEAD + h] = make_float2(m_i[i], l_i[i]);
        }
    }
}

// ---------------------------------------------------------------------------
// Combine partial-softmax chunks: O = (O0*w0 + O1*w1) / (l0*w0 + l1*w1)
// ---------------------------------------------------------------------------
__global__ void combine_kernel(
    const float* __restrict__ Op0, const float* __restrict__ Op1,
    const float2* __restrict__ ml0, const float2* __restrict__ ml1,
    float* __restrict__ O, const int* __restrict__ channels, int nseg, int T)
{
    const int idx = blockIdx.x * blockDim.x + threadIdx.x;   // one float4 each
    const int total = T * DMODEL / 4;
    if (idx >= total) return;

    const int token = idx / (DMODEL / 4);
    const int h = (idx % (DMODEL / 4)) / (HDIM / 4);

    int csum = 0;
    for (int i = 0; i < nseg; i++) csum += channels[i];
    const int Stok = T / csum;

    int nc = 1;
    {
        int soff = 0;
        for (int i = 0; i < nseg; i++) {
            int L = channels[i] * Stok;
            if (token < soff + L) {
                int nkt = (L + 63) >> 6;
                nc = (nkt > CHUNK_THRESH) ? 2 : 1;
                break;
            }
            soff += L;
        }
    }

    float4 o0 = ((const float4*)Op0)[idx];
    float2 a = ml0[token * NHEAD + h];
    float4 out;
    if (nc == 1) {
        float inv = 1.0f / a.y;
        out = make_float4(o0.x * inv, o0.y * inv, o0.z * inv, o0.w * inv);
    } else {
        float4 o1 = ((const float4*)Op1)[idx];
        float2 b = ml1[token * NHEAD + h];
        float m = fmaxf(a.x, b.x);
        float w0 = __expf(a.x - m);
        float w1 = __expf(b.x - m);
        float inv = 1.0f / (a.y * w0 + b.y * w1);
        out.x = (o0.x * w0 + o1.x * w1) * inv;
        out.y = (o0.y * w0 + o1.y * w1) * inv;
        out.z = (o0.z * w0 + o1.z * w1) * inv;
        out.w = (o0.w * w0 + o1.w * w1) * inv;
    }
    ((float4*)O)[idx] = out;
}

// ---------------------------------------------------------------------------
extern "C" void kernel_launch(void* const* d_in, const int* in_sizes, int n_in,
                              void* d_out, int out_size)
{
    const float* xq  = (const float*)d_in[0];
    const float* xk  = (const float*)d_in[1];
    const float* pos = (const float*)d_in[2];
    const int* channels = (const int*)d_in[3];
    const float* Wq = (const float*)d_in[4];  const float* bq = (const float*)d_in[5];
    const float* Wk = (const float*)d_in[6];  const float* bk = (const float*)d_in[7];
    const float* Wv = (const float*)d_in[8];  const float* bv = (const float*)d_in[9];
    const float* Wo = (const float*)d_in[10]; const float* bo = (const float*)d_in[11];

    const int T = in_sizes[0] / DMODEL;     // 3136
    const int nseg = in_sizes[3];           // 4

    float *pQ, *pK, *pV, *pO, *pOp0, *pOp1;
    float2 *pml0, *pml1;
    cudaGetSymbolAddress((void**)&pQ, g_Q);
    cudaGetSymbolAddress((void**)&pK, g_K);
    cudaGetSymbolAddress((void**)&pV, g_V);
    cudaGetSymbolAddress((void**)&pO, g_O);
    cudaGetSymbolAddress((void**)&pOp0, g_Op0);
    cudaGetSymbolAddress((void**)&pOp1, g_Op1);
    cudaGetSymbolAddress((void**)&pml0, g_ml0);
    cudaGetSymbolAddress((void**)&pml1, g_ml1);

    dim3 blk(256);
    dim3 grd(T / 64, DMODEL / 64);

    gemm_proj<<<grd, blk>>>(xq, pos, Wq, bq, pQ, T);
    gemm_proj<<<grd, blk>>>(xk, pos, Wk, bk, pK, T);
    gemm_proj<<<grd, blk>>>(xk, nullptr, Wv, bv, pV, T);

    cudaFuncSetAttribute(attn_kernel, cudaFuncAttributeMaxDynamicSharedMemorySize,
                         (int)ATTN_SMEM);
    dim3 agrd(2 * (T / 64) + nseg, NHEAD);   // upper bound; extras exit early
    attn_kernel<<<agrd, blk, ATTN_SMEM>>>(pQ, pK, pV, pOp0, pOp1, pml0, pml1,
                                          channels, nseg, T);

    const int total4 = T * DMODEL / 4;
    combine_kernel<<<(total4 + 255) / 256, 256>>>(pOp0, pOp1, pml0, pml1, pO,
                                                  channels, nseg, T);

    gemm_proj<<<grd, blk>>>(pO, nullptr, Wo, bo, (float*)d_out, T);
}